// round 15
// baseline (speedup 1.0000x reference)
#include <cuda_runtime.h>

// FINAL (R12 revert — measured optimum of the search):
// Plain-LDG streaming + single-wave grid + warp-shuffle for the shifted
// pred element. 888 CTAs (148 SMs x 6 CTAs @ 36 regs) = exactly one wave;
// unroll 4; dual accumulators; __ldcs on single-use x/y streams; fused
// "last block finishes" finalize. Deterministic, graph-replay safe.
//
// Measured: 27.87 us = 7.22 TB/s effective (~90% of 8 TB/s spec).
// Perturbations measured and rejected: unroll 8 (regs 48, -12%), regs=32
// via launch_bounds(,7) (-5%), regs=40 via launch_bounds(,6) (-1%),
// TMA pipelines / dual-engine / ticket scheduler (all >= +25% slower),
// asm-pinned loads (-14%).

static constexpr int BLOCKS  = 148 * 6;   // 888 CTAs = exactly 1 wave @ 36 regs
static constexpr int THREADS = 256;

__device__ float        g_partials[BLOCKS];
__device__ unsigned int g_done_count;      // zero-init; reset each call

__global__ __launch_bounds__(THREADS) void trajloss_wave_kernel(
    const float* __restrict__ pred,   // N+1 elements
    const float* __restrict__ xs,     // N elements
    const float* __restrict__ ys,     // N elements
    float* __restrict__ out,
    int n4)                           // N / 4
{
    const float4* __restrict__ pred4 = reinterpret_cast<const float4*>(pred);
    const float4* __restrict__ x4    = reinterpret_cast<const float4*>(xs);
    const float4* __restrict__ y4    = reinterpret_cast<const float4*>(ys);

    float acc0 = 0.0f, acc1 = 0.0f;

    const int stride = BLOCKS * THREADS;
    const int lane   = threadIdx.x & 31;
    int idx = blockIdx.x * THREADS + threadIdx.x;

    // stride % 32 == 0 and warp bases are 32-aligned -> multiple-of-32 bound
    // keeps the loop guard warp-uniform (shuffle-safe).
    const int bound = n4 & ~31;

    #pragma unroll 4
    for (int i = idx; i < bound; i += stride) {
        float4 p  = pred4[i];
        float4 xv = __ldcs(&x4[i]);
        float4 yv = __ldcs(&y4[i]);

        // pred[4i+4] = next lane's p.x; lane 31 loads across the warp boundary.
        float pn = __shfl_down_sync(0xFFFFFFFFu, p.x, 1);
        if (lane == 31) pn = __ldg(&pred[i * 4 + 4]);

        float dx0 = xv.x - p.x, dx1 = xv.y - p.y;
        float dx2 = xv.z - p.z, dx3 = xv.w - p.w;
        float dy0 = yv.x - p.y, dy1 = yv.y - p.z;
        float dy2 = yv.z - p.w, dy3 = yv.w - pn;

        acc0 = fmaf(dx0, dx0, acc0); acc1 = fmaf(dy0, dy0, acc1);
        acc0 = fmaf(dx1, dx1, acc0); acc1 = fmaf(dy1, dy1, acc1);
        acc0 = fmaf(dx2, dx2, acc0); acc1 = fmaf(dy2, dy2, acc1);
        acc0 = fmaf(dx3, dx3, acc0); acc1 = fmaf(dy3, dy3, acc1);
    }

    // Shuffle-free remainder (zero iterations for N = 2^24).
    for (int i = (idx >= bound ? idx : idx + ((bound - idx + stride - 1) / stride) * stride);
         i < n4; i += stride) {
        float4 p  = pred4[i];
        float4 xv = __ldcs(&x4[i]);
        float4 yv = __ldcs(&y4[i]);
        float  pn = __ldg(&pred[i * 4 + 4]);

        float dx0 = xv.x - p.x, dx1 = xv.y - p.y;
        float dx2 = xv.z - p.z, dx3 = xv.w - p.w;
        float dy0 = yv.x - p.y, dy1 = yv.y - p.z;
        float dy2 = yv.z - p.w, dy3 = yv.w - pn;

        acc0 = fmaf(dx0, dx0, acc0); acc1 = fmaf(dy0, dy0, acc1);
        acc0 = fmaf(dx1, dx1, acc0); acc1 = fmaf(dy1, dy1, acc1);
        acc0 = fmaf(dx2, dx2, acc0); acc1 = fmaf(dy2, dy2, acc1);
        acc0 = fmaf(dx3, dx3, acc0); acc1 = fmaf(dy3, dy3, acc1);
    }

    float acc = acc0 + acc1;

    // ---- intra-block reduction ----
    #pragma unroll
    for (int off = 16; off > 0; off >>= 1)
        acc += __shfl_xor_sync(0xFFFFFFFFu, acc, off);

    __shared__ float warp_sums[THREADS / 32];
    __shared__ bool  is_last;
    int wid = threadIdx.x >> 5;
    if (lane == 0) warp_sums[wid] = acc;
    __syncthreads();

    if (wid == 0) {
        float v = (lane < THREADS / 32) ? warp_sums[lane] : 0.0f;
        #pragma unroll
        for (int off = 4; off > 0; off >>= 1)
            v += __shfl_xor_sync(0xFFFFFFFFu, v, off);
        if (lane == 0) {
            g_partials[blockIdx.x] = v;
            __threadfence();
            unsigned int prev = atomicAdd(&g_done_count, 1u);
            is_last = (prev == (unsigned int)(BLOCKS - 1));
        }
    }
    __syncthreads();

    // ---- last block reduces all partials ----
    if (is_last) {
        float t = 0.0f;
        for (int k = threadIdx.x; k < BLOCKS; k += THREADS)
            t += g_partials[k];

        #pragma unroll
        for (int off = 16; off > 0; off >>= 1)
            t += __shfl_xor_sync(0xFFFFFFFFu, t, off);

        if (lane == 0) warp_sums[wid] = t;
        __syncthreads();

        if (wid == 0) {
            float v = (lane < THREADS / 32) ? warp_sums[lane] : 0.0f;
            #pragma unroll
            for (int off = 4; off > 0; off >>= 1)
                v += __shfl_xor_sync(0xFFFFFFFFu, v, off);
            if (lane == 0) {
                out[0] = v;
                g_done_count = 0;     // graph-replay safe reset
            }
        }
    }
}

extern "C" void kernel_launch(void* const* d_in, const int* in_sizes, int n_in,
                              void* d_out, int out_size)
{
    const float* pred = (const float*)d_in[0];   // N+1
    const float* xs   = (const float*)d_in[1];   // N
    const float* ys   = (const float*)d_in[2];   // N
    float* out        = (float*)d_out;

    int n  = in_sizes[1];
    int n4 = n >> 2;

    trajloss_wave_kernel<<<BLOCKS, THREADS>>>(pred, xs, ys, out, n4);
}

// round 17
// speedup vs baseline: 1.0228x; 1.0228x over previous
#include <cuda_runtime.h>

// FINAL — converged optimum of the 15-round search.
// Plain-LDG streaming + single-wave grid + warp-shuffle for the shifted
// pred element. 888 CTAs (148 SMs x 6 CTAs @ 36 regs) = exactly one wave;
// unroll 4; dual accumulators; __ldcs on single-use x/y streams; fused
// "last block finishes" finalize. Deterministic, graph-replay safe.
//
// Measured: 27.87 / 28.74 us across two identical-source runs
// (run-to-run noise ~±0.9 us) = 7.0-7.2 TB/s effective, ~90% of HBM spec.
// Rejected by measurement: unroll 8 (-12%), regs=32 (-5%), regs=40 (-1%),
// TMA pipeline / dual-engine / ticket scheduler (all >= +25%),
// asm-pinned load batching (-14%), 1184-CTA two-wave grid (-11%).

static constexpr int BLOCKS  = 148 * 6;   // 888 CTAs = exactly 1 wave @ 36 regs
static constexpr int THREADS = 256;

__device__ float        g_partials[BLOCKS];
__device__ unsigned int g_done_count;      // zero-init; reset each call

__global__ __launch_bounds__(THREADS) void trajloss_wave_kernel(
    const float* __restrict__ pred,   // N+1 elements
    const float* __restrict__ xs,     // N elements
    const float* __restrict__ ys,     // N elements
    float* __restrict__ out,
    int n4)                           // N / 4
{
    const float4* __restrict__ pred4 = reinterpret_cast<const float4*>(pred);
    const float4* __restrict__ x4    = reinterpret_cast<const float4*>(xs);
    const float4* __restrict__ y4    = reinterpret_cast<const float4*>(ys);

    float acc0 = 0.0f, acc1 = 0.0f;

    const int stride = BLOCKS * THREADS;
    const int lane   = threadIdx.x & 31;
    int idx = blockIdx.x * THREADS + threadIdx.x;

    // stride % 32 == 0 and warp bases are 32-aligned -> multiple-of-32 bound
    // keeps the loop guard warp-uniform (shuffle-safe).
    const int bound = n4 & ~31;

    #pragma unroll 4
    for (int i = idx; i < bound; i += stride) {
        float4 p  = pred4[i];
        float4 xv = __ldcs(&x4[i]);
        float4 yv = __ldcs(&y4[i]);

        // pred[4i+4] = next lane's p.x; lane 31 loads across the warp boundary.
        float pn = __shfl_down_sync(0xFFFFFFFFu, p.x, 1);
        if (lane == 31) pn = __ldg(&pred[i * 4 + 4]);

        float dx0 = xv.x - p.x, dx1 = xv.y - p.y;
        float dx2 = xv.z - p.z, dx3 = xv.w - p.w;
        float dy0 = yv.x - p.y, dy1 = yv.y - p.z;
        float dy2 = yv.z - p.w, dy3 = yv.w - pn;

        acc0 = fmaf(dx0, dx0, acc0); acc1 = fmaf(dy0, dy0, acc1);
        acc0 = fmaf(dx1, dx1, acc0); acc1 = fmaf(dy1, dy1, acc1);
        acc0 = fmaf(dx2, dx2, acc0); acc1 = fmaf(dy2, dy2, acc1);
        acc0 = fmaf(dx3, dx3, acc0); acc1 = fmaf(dy3, dy3, acc1);
    }

    // Shuffle-free remainder (zero iterations for N = 2^24).
    for (int i = (idx >= bound ? idx : idx + ((bound - idx + stride - 1) / stride) * stride);
         i < n4; i += stride) {
        float4 p  = pred4[i];
        float4 xv = __ldcs(&x4[i]);
        float4 yv = __ldcs(&y4[i]);
        float  pn = __ldg(&pred[i * 4 + 4]);

        float dx0 = xv.x - p.x, dx1 = xv.y - p.y;
        float dx2 = xv.z - p.z, dx3 = xv.w - p.w;
        float dy0 = yv.x - p.y, dy1 = yv.y - p.z;
        float dy2 = yv.z - p.w, dy3 = yv.w - pn;

        acc0 = fmaf(dx0, dx0, acc0); acc1 = fmaf(dy0, dy0, acc1);
        acc0 = fmaf(dx1, dx1, acc0); acc1 = fmaf(dy1, dy1, acc1);
        acc0 = fmaf(dx2, dx2, acc0); acc1 = fmaf(dy2, dy2, acc1);
        acc0 = fmaf(dx3, dx3, acc0); acc1 = fmaf(dy3, dy3, acc1);
    }

    float acc = acc0 + acc1;

    // ---- intra-block reduction ----
    #pragma unroll
    for (int off = 16; off > 0; off >>= 1)
        acc += __shfl_xor_sync(0xFFFFFFFFu, acc, off);

    __shared__ float warp_sums[THREADS / 32];
    __shared__ bool  is_last;
    int wid = threadIdx.x >> 5;
    if (lane == 0) warp_sums[wid] = acc;
    __syncthreads();

    if (wid == 0) {
        float v = (lane < THREADS / 32) ? warp_sums[lane] : 0.0f;
        #pragma unroll
        for (int off = 4; off > 0; off >>= 1)
            v += __shfl_xor_sync(0xFFFFFFFFu, v, off);
        if (lane == 0) {
            g_partials[blockIdx.x] = v;
            __threadfence();
            unsigned int prev = atomicAdd(&g_done_count, 1u);
            is_last = (prev == (unsigned int)(BLOCKS - 1));
        }
    }
    __syncthreads();

    // ---- last block reduces all partials ----
    if (is_last) {
        float t = 0.0f;
        for (int k = threadIdx.x; k < BLOCKS; k += THREADS)
            t += g_partials[k];

        #pragma unroll
        for (int off = 16; off > 0; off >>= 1)
            t += __shfl_xor_sync(0xFFFFFFFFu, t, off);

        if (lane == 0) warp_sums[wid] = t;
        __syncthreads();

        if (wid == 0) {
            float v = (lane < THREADS / 32) ? warp_sums[lane] : 0.0f;
            #pragma unroll
            for (int off = 4; off > 0; off >>= 1)
                v += __shfl_xor_sync(0xFFFFFFFFu, v, off);
            if (lane == 0) {
                out[0] = v;
                g_done_count = 0;     // graph-replay safe reset
            }
        }
    }
}

extern "C" void kernel_launch(void* const* d_in, const int* in_sizes, int n_in,
                              void* d_out, int out_size)
{
    const float* pred = (const float*)d_in[0];   // N+1
    const float* xs   = (const float*)d_in[1];   // N
    const float* ys   = (const float*)d_in[2];   // N
    float* out        = (float*)d_out;

    int n  = in_sizes[1];
    int n4 = n >> 2;

    trajloss_wave_kernel<<<BLOCKS, THREADS>>>(pred, xs, ys, out, n4);
}